// round 12
// baseline (speedup 1.0000x reference)
#include <cuda_runtime.h>
#include <cuda_bf16.h>
#include <math.h>
#include <stdint.h>

#define NB 2
#define NN 256
#define NC 5
#define NFF 20

__device__ float    g_part[NC*NB*NN];   // planar [c][row]
__device__ unsigned g_t1[16];           // hierarchical ticket, level 1
__device__ unsigned g_t2 = 0;           // level 2

__device__ __forceinline__ float gelu_t(float x){
    float z = 1.5957691216057308f*fmaf(0.044715f*x, x*x, x);
    return __fdividef(x, 1.0f + __expf(-z));
}
__device__ __forceinline__ float wredsum(float v){
    #pragma unroll
    for (int o=16;o;o>>=1) v += __shfl_xor_sync(0xffffffffu, v, o);
    return v;
}
__device__ __forceinline__ float wredmax(float v){
    #pragma unroll
    for (int o=16;o;o>>=1) v = fmaxf(v, __shfl_xor_sync(0xffffffffu, v, o));
    return v;
}
__device__ __forceinline__ bool adjval(const void* a, int mode, int idx){
    if (mode == 1) return ((const int*)a)[idx] != 0;
    if (mode == 2) return ((const float*)a)[idx] != 0.f;
    return ((const unsigned char*)a)[idx] != 0;
}

// Slow (exact, general) logit evaluator — fallback only.
template<int K>
__device__ __forceinline__ void logits_eval(
    int M, int el, int h,
    const float* __restrict__ shDist, const float* __restrict__ shY,
    const float2* __restrict__ shR1b,
    const float* __restrict__ shA, const float* __restrict__ shA0p,
    float (*__restrict__ shLp)[4])
{
    float dist[K], yc[K];
    float4 y4[K];
    bool  val[K];
    #pragma unroll
    for (int k=0;k<K;k++){
        int e = el + 64*k;
        val[k] = (e < M);
        if (val[k]){
            dist[k] = shDist[e];
            y4[k] = *(const float4*)&shY[e*8];
            yc[k] = shY[e*8+4];
        } else {
            dist[k]=0.f; y4[k]=make_float4(0.f,0.f,0.f,0.f); yc[k]=0.f;
        }
    }
    float acc[K];
    #pragma unroll
    for (int k=0;k<K;k++) acc[k]=0.f;
    const float* Ah = shA + h*256;
    #pragma unroll 8
    for (int t=0;t<32;t++){
        float2 rb = shR1b[t];
        float4 a  = *(const float4*)&Ah[t*8];
        float  a4 = Ah[t*8+4];
        #pragma unroll
        for (int k=0;k<K;k++){
            float hv = fmaxf(fmaf(dist[k], rb.x, rb.y), 0.f);
            float tmp = fmaf(y4[k].x,a.x, fmaf(y4[k].y,a.y,
                        fmaf(y4[k].z,a.z, fmaf(y4[k].w,a.w, yc[k]*a4))));
            acc[k] = fmaf(hv, tmp, acc[k]);
        }
    }
    float4 a0 = *(const float4*)&shA0p[h*8];
    float a04 = shA0p[h*8+4];
    #pragma unroll
    for (int k=0;k<K;k++){
        if (val[k]){
            float l = acc[k] + fmaf(y4[k].x,a0.x, fmaf(y4[k].y,a0.y,
                      fmaf(y4[k].z,a0.z, fmaf(y4[k].w,a0.w, yc[k]*a04))));
            shLp[el+64*k][h] = l*0.35355339059327373f;
        }
    }
}

// ---------------------------------------------------------------------------
__global__ void __launch_bounds__(256,4)
attn_fused(const float* __restrict__ feats, const float* __restrict__ coors,
           const void*  __restrict__ adj,
           const float* __restrict__ Wq,  const float* __restrict__ Mk,
           const float* __restrict__ Mv,
           const float* __restrict__ R1,  const float* __restrict__ rb1,
           const float* __restrict__ R2,  const float* __restrict__ rb2,
           const float* __restrict__ Wo0,
           const float* __restrict__ gnA, const float* __restrict__ bnA,
           const float* __restrict__ gnF, const float* __restrict__ bnF,
           const float* __restrict__ Wf1, const float* __restrict__ Wf2,
           const float* __restrict__ Wh1, const float* __restrict__ bh1,
           const float* __restrict__ Wh2, const float* __restrict__ bh2,
           float* __restrict__ out){
    __shared__ float shR2k[1024], shR2v[1024];          // staged in prologue (both paths)
    __shared__ float shMv[160], shWo[160], shqMk[160];
    __shared__ float2 shR1b[32];
    __shared__ float shrb2k[32], shrb2v[32], shq[32];
    __shared__ __align__(16) float shA[4*256];          // slow
    __shared__ __align__(16) float shA0p[32];           // slow
    __shared__ float shS[4*164];                        // slow
    __shared__ float shS0[4][5];                        // slow
    __shared__ __align__(16) float shY[256*8];
    __shared__ float shDist[256];
    __shared__ __align__(16) float shLp[256][4];
    __shared__ unsigned shlanes[8];
    __shared__ int shcnt[8];
    __shared__ unsigned char shdir[256], shlist[256];
    __shared__ float shred[8][5];
    __shared__ float shmax[4], shsum[4];
    __shared__ float shC[4][32];                        // Ck,Pk,Cv,Pv
    __shared__ float shLQ[20], shLPb[20];               // [h*5+c]
    __shared__ float shTD[44];                          // [0..3]=sum, [4..23]=T, [24..43]=D
    __shared__ unsigned sh_is_last;
    __shared__ float sp[NB][NC];
    __shared__ float shh[NB][128];

    int row = blockIdx.x;
    int b = row >> 8, i = row & 255;
    int tid = threadIdx.x;
    int lane = tid & 31, wp = tid >> 5;

    // ---- prologue: stage ALL weights + dtype detect + q0 ----
    for (int s=tid; s<1024; s+=256){
        int t = s >> 5, hd = s & 31;
        shR2k[s] = R2[t*384 + hd];
        shR2v[s] = R2[t*384 + 192 + hd];
    }
    if (tid < 160){ shMv[tid] = Mv[tid]; shWo[tid] = Wo0[tid]; }
    if (tid < 32){
        shR1b[tid] = make_float2(R1[tid], rb1[tid]);
        shrb2k[tid]=rb2[tid]; shrb2v[tid]=rb2[192+tid];
    }
    {
        unsigned m = 0;
        const uint32_t* aw = (const uint32_t*)adj;
        #pragma unroll
        for (int o=0;o<4;o++){
            uint32_t w = aw[o*256 + tid];
            m |= (w & 0x000000FFu ? 1u:0u) | (w & 0x0000FF00u ? 2u:0u)
               | (w & 0x00FF0000u ? 4u:0u) | (w & 0xFF000000u ? 8u:0u);
        }
        #pragma unroll
        for (int off=16; off; off>>=1) m |= __shfl_xor_sync(0xffffffffu, m, off);
        if (lane == 0) shlanes[wp] = m;
    }
    if (tid >= 32 && tid < 64){            // q0
        int hd = tid - 32;
        float xv[NC], n0[NC], mu = 0.f;
        #pragma unroll
        for (int c=0;c<NC;c++){ xv[c]=feats[row*NC+c]; n0[c]=fabsf(xv[c]); mu += n0[c]; }
        mu *= 0.2f;
        float var = 0.f;
        #pragma unroll
        for (int c=0;c<NC;c++){ float d=n0[c]-mu; var = fmaf(d,d,var); }
        var *= 0.2f;
        float isd = __fdividef(1.f, sqrtf(var) + 1e-8f);
        float q = 0.f;
        #pragma unroll
        for (int c=0;c<NC;c++){
            float ln = (n0[c]-mu)*isd * gnA[c] + bnA[c];
            float g = gelu_t(ln);
            float y = (xv[c] > 0.f) ? g : ((xv[c] < 0.f) ? -g : 0.f);
            q = fmaf(y, Wq[c*32+hd], q);
        }
        shq[hd] = q;
    }
    __syncthreads();

    unsigned lm = 0;
    #pragma unroll
    for (int w=0; w<8; w++) lm |= shlanes[w];
    int mode = ((lm & 0xEu) == 0) ? 1 : (((lm & 0x3u) == 0) ? 2 : 0);

    if (tid < 160) shqMk[tid] = shq[tid & 31] * Mk[tid];

    // ---- adjacency: direct row -> dir list (32-bit indices) ----
    bool okd = adjval(adj, mode, row*NN + tid);
    unsigned bald = __ballot_sync(0xffffffffu, okd);
    if (lane == 0) shcnt[wp] = __popc(bald);
    __syncthreads();
    int based = 0, Mdir = 0;
    #pragma unroll
    for (int w=0; w<8; w++){ if (w < wp) based += shcnt[w]; Mdir += shcnt[w]; }
    if (okd) shdir[based + __popc(bald & ((1u<<lane)-1u))] = (unsigned char)tid;
    __syncthreads();

    // ---- 2-hop: per-thread OR, clamped unroll-8 for MLP ----
    bool col2 = false;
    {
        int bb = b*NN*NN;
        for (int d0 = 0; d0 < Mdir; d0 += 8){
            #pragma unroll
            for (int k=0;k<8;k++){
                int d = d0 + k;
                int dd = (d < Mdir) ? d : (Mdir - 1);
                bool v = adjval(adj, mode, bb + (int)shdir[dd]*NN + tid);
                col2 |= (d < Mdir) & v;
            }
        }
    }
    bool ok = okd | col2 | (tid == i);

    // compaction of active j's (ascending)
    unsigned bal = __ballot_sync(0xffffffffu, ok);
    if (lane == 0) shcnt[wp] = __popc(bal);
    __syncthreads();
    int base = 0, M = 0;
    #pragma unroll
    for (int w=0; w<8; w++){ if (w < wp) base += shcnt[w]; M += shcnt[w]; }
    if (ok) shlist[base + __popc(bal & ((1u<<lane)-1u))] = (unsigned char)tid;
    __syncthreads();

    // ---- E1: per-edge dist + normalized y[5] ----
    bool act_e = (tid < M);
    float y5[5] = {0.f,0.f,0.f,0.f,0.f};
    float de = 0.f;
    {
        float cx = coors[row*3+0], cy = coors[row*3+1], cz = coors[row*3+2];
        if (act_e){
            int jr = (b << 8) + (int)shlist[tid];
            float dx = cx - coors[jr*3+0];
            float dy = cy - coors[jr*3+1];
            float dz = cz - coors[jr*3+2];
            de = sqrtf(fmaf(dx,dx,fmaf(dy,dy,fmaf(dz,dz,1e-12f))));
            shDist[tid] = de;
            float xv[NC], n0[NC], mu = 0.f;
            #pragma unroll
            for (int c=0;c<NC;c++){ xv[c]=feats[jr*NC+c]; n0[c]=fabsf(xv[c]); mu += n0[c]; }
            mu *= 0.2f;
            float var = 0.f;
            #pragma unroll
            for (int c=0;c<NC;c++){ float d=n0[c]-mu; var = fmaf(d,d,var); }
            var *= 0.2f;
            float isd = __fdividef(1.f, sqrtf(var) + 1e-8f);
            #pragma unroll
            for (int c=0;c<NC;c++){
                float ln = (n0[c]-mu)*isd * gnA[c] + bnA[c];
                float g = gelu_t(ln);
                y5[c] = (xv[c] > 0.f) ? g : ((xv[c] < 0.f) ? -g : 0.f);
                shY[tid*8+c] = y5[c];
            }
        }
        float dmn = act_e ? de : 1e30f;
        float dmx = act_e ? de : -1e30f;
        #pragma unroll
        for (int o=16;o;o>>=1){
            dmn = fminf(dmn, __shfl_xor_sync(0xffffffffu, dmn, o));
            dmx = fmaxf(dmx, __shfl_xor_sync(0xffffffffu, dmx, o));
        }
        if (lane == 0){ shred[wp][0] = dmn; shred[wp][1] = dmx; }
    }
    __syncthreads();

    // ---- linearity check: redundantly in EVERY warp ----
    unsigned actm;
    bool slow;
    {
        float dmin = 1e30f, dmax = -1e30f;
        #pragma unroll
        for (int w=0; w<8; w++){
            dmin = fminf(dmin, shred[w][0]);
            dmax = fmaxf(dmax, shred[w][1]);
        }
        float2 rb = shR1b[lane];
        float x1 = fmaf(dmin, rb.x, rb.y);
        float x2 = fmaf(dmax, rb.x, rb.y);
        float xlo = fminf(x1,x2), xhi = fmaxf(x1,x2);
        actm = __ballot_sync(0xffffffffu, xhi > 0.f);
        unsigned badm = __ballot_sync(0xffffffffu, (xlo < 0.f) && (xhi > 0.f));
        slow = (badm != 0u);
    }

    float oval = 0.f;   // warp-0 per-lane o0[lane], set by either path

    if (!slow){
        // ================= FAST (linear) PATH =================
        if (tid < 128){
            int kind = tid >> 5, hd = tid & 31;
            const float* src = (kind < 2) ? shR2k : shR2v;
            float acc = 0.f;
            #pragma unroll 4
            for (int t=0; t<32; t++){
                if ((actm >> t) & 1u){
                    float2 rb = shR1b[t];
                    float w = (kind & 1) ? rb.y : rb.x;
                    acc = fmaf(w, src[t*32 + hd], acc);
                }
            }
            shC[kind][hd] = acc;
        }
        __syncthreads();
        if (tid < 20){
            int h = tid / 5, c = tid - h*5;
            float lq = 0.f, lp = 0.f;
            #pragma unroll
            for (int dd=0; dd<8; dd++){
                float qm = shqMk[c*32 + h*8 + dd];
                lq = fmaf(qm, shC[0][h*8+dd], lq);
                lp = fmaf(qm, shrb2k[h*8+dd] + shC[1][h*8+dd], lp);
            }
            shLQ[tid] = lq; shLPb[tid] = lp;
        }
        __syncthreads();

        // logits in registers
        float lg[4];
        #pragma unroll
        for (int h=0; h<4; h++){
            float l = 0.f;
            #pragma unroll
            for (int c=0; c<5; c++)
                l = fmaf(y5[c], fmaf(de, shLQ[h*5+c], shLPb[h*5+c]), l);
            lg[h] = act_e ? l*0.35355339059327373f : -1e30f;
        }
        #pragma unroll
        for (int h=0; h<4; h++){
            float mm = wredmax(lg[h]);
            if (lane == 0) shred[wp][h] = mm;
        }
        __syncthreads();
        if (tid < 4){
            float mm = -1e30f;
            #pragma unroll
            for (int w=0; w<8; w++) mm = fmaxf(mm, shred[w][tid]);
            shmax[tid] = mm;
        }
        __syncthreads();
        if (act_e){
            float4 L;
            L.x = __expf(lg[0]-shmax[0]);
            L.y = __expf(lg[1]-shmax[1]);
            L.z = __expf(lg[2]-shmax[2]);
            L.w = __expf(lg[3]-shmax[3]);
            *(float4*)&shLp[tid][0] = L;
        }
        __syncthreads();

        // moments via smem-transpose consumers
        if (tid < 160){
            int g = tid >> 3, ch = tid & 7;
            int h = g/5, c = g - h*5;
            float T = 0.f, D = 0.f;
            for (int e = ch; e < M; e += 8){
                float ly = shLp[e][h]*shY[e*8+c];
                T += ly;
                D = fmaf(ly, shDist[e], D);
            }
            #pragma unroll
            for (int o=1; o<8; o<<=1){
                T += __shfl_xor_sync(0xffffffffu, T, o);
                D += __shfl_xor_sync(0xffffffffu, D, o);
            }
            if (ch == 0){ shTD[4+g] = T; shTD[24+g] = D; }
        } else if (tid < 192){
            int k = tid - 160;
            int h = k >> 3, ch = k & 7;
            float s = 0.f;
            for (int e = ch; e < M; e += 8) s += shLp[e][h];
            #pragma unroll
            for (int o=1; o<8; o<<=1) s += __shfl_xor_sync(0xffffffffu, s, o);
            if (ch == 0) shTD[h] = s;
        }
        __syncthreads();

        if (wp == 0){
            int hh = lane >> 3;
            float cst = shrb2v[lane] + shC[3][lane];   // rb2v + Pv
            float cv  = shC[2][lane];                  // Cv
            float o = 0.f;
            #pragma unroll
            for (int c=0;c<5;c++)
                o = fmaf(shMv[c*32+lane],
                         fmaf(cst, shTD[4+hh*5+c], cv*shTD[24+hh*5+c]), o);
            oval = __fdividef(o, shTD[hh]);
        }
    } else {
        // ================= SLOW (exact) PATH =================
        for (int idx = tid; idx < 660; idx += 256){
            if (idx < 640){
                int h = idx / 160, r = idx - h*160, t = r/5, c = r - t*5;
                float s = 0.f;
                #pragma unroll
                for (int d=0; d<8; d++)
                    s = fmaf(shqMk[c*32 + h*8 + d], shR2k[t*32 + h*8 + d], s);
                shA[h*256 + t*8 + c] = s;
            } else {
                int k = idx - 640, h = k/5, c = k - h*5;
                float s = 0.f;
                #pragma unroll
                for (int d=0; d<8; d++)
                    s = fmaf(shqMk[c*32 + h*8 + d], shrb2k[h*8 + d], s);
                shA0p[h*8 + c] = s;
            }
        }
        if (act_e){ shY[tid*8+5]=0.f; shY[tid*8+6]=0.f; shY[tid*8+7]=0.f; }
        __syncthreads();
        {
            int h = tid & 3;
            int el = tid >> 2;
            int kmax = (M + 63) >> 6;
            switch (kmax){
                case 1: logits_eval<1>(M, el, h, shDist, shY, shR1b, shA, shA0p, shLp); break;
                case 2: logits_eval<2>(M, el, h, shDist, shY, shR1b, shA, shA0p, shLp); break;
                case 3: logits_eval<3>(M, el, h, shDist, shY, shR1b, shA, shA0p, shLp); break;
                default: logits_eval<4>(M, el, h, shDist, shY, shR1b, shA, shA0p, shLp); break;
            }
        }
        __syncthreads();
        {
            float4 lv4 = (tid < M) ? *(const float4*)&shLp[tid][0]
                                   : make_float4(-1e30f,-1e30f,-1e30f,-1e30f);
            float lv[4] = {lv4.x, lv4.y, lv4.z, lv4.w};
            #pragma unroll
            for (int hh=0; hh<4; hh++){
                float mm = wredmax(lv[hh]);
                if (lane == 0) shred[wp][hh] = mm;
            }
            __syncthreads();
            if (tid < 4){
                float mm = -1e30f;
                #pragma unroll
                for (int w=0; w<8; w++) mm = fmaxf(mm, shred[w][tid]);
                shmax[tid] = mm;
            }
            __syncthreads();
            float ex[4];
            #pragma unroll
            for (int hh=0; hh<4; hh++) ex[hh] = (tid < M) ? __expf(lv[hh]-shmax[hh]) : 0.f;
            if (tid < M)
                *(float4*)&shLp[tid][0] = make_float4(ex[0],ex[1],ex[2],ex[3]);
            #pragma unroll
            for (int hh=0; hh<4; hh++){
                float ss = wredsum(ex[hh]);
                if (lane == 0) shred[wp][hh] = ss;
            }
            __syncthreads();
            if (tid < 4){
                float ss = 0.f;
                #pragma unroll
                for (int w=0; w<8; w++) ss += shred[w][tid];
                shsum[tid] = ss;
            }
            __syncthreads();
        }
        {
            int chunk = tid & 7, t = tid >> 3;
            float2 rb = shR1b[t];
            float acc[20];
            #pragma unroll
            for (int k=0;k<20;k++) acc[k]=0.f;
            for (int e = chunk; e < M; e += 8){
                float hv = fmaxf(fmaf(shDist[e], rb.x, rb.y), 0.f);
                float4 L4 = *(const float4*)&shLp[e][0];
                float4 y4 = *(const float4*)&shY[e*8];
                float  yc = shY[e*8+4];
                float p0 = L4.x*hv, p1 = L4.y*hv, p2 = L4.z*hv, p3 = L4.w*hv;
                acc[0] = fmaf(p0,y4.x,acc[0]);  acc[1] = fmaf(p0,y4.y,acc[1]);
                acc[2] = fmaf(p0,y4.z,acc[2]);  acc[3] = fmaf(p0,y4.w,acc[3]);
                acc[4] = fmaf(p0,yc,  acc[4]);
                acc[5] = fmaf(p1,y4.x,acc[5]);  acc[6] = fmaf(p1,y4.y,acc[6]);
                acc[7] = fmaf(p1,y4.z,acc[7]);  acc[8] = fmaf(p1,y4.w,acc[8]);
                acc[9] = fmaf(p1,yc,  acc[9]);
                acc[10]= fmaf(p2,y4.x,acc[10]); acc[11]= fmaf(p2,y4.y,acc[11]);
                acc[12]= fmaf(p2,y4.z,acc[12]); acc[13]= fmaf(p2,y4.w,acc[13]);
                acc[14]= fmaf(p2,yc,  acc[14]);
                acc[15]= fmaf(p3,y4.x,acc[15]); acc[16]= fmaf(p3,y4.y,acc[16]);
                acc[17]= fmaf(p3,y4.z,acc[17]); acc[18]= fmaf(p3,y4.w,acc[18]);
                acc[19]= fmaf(p3,yc,  acc[19]);
            }
            #pragma unroll
            for (int k=0;k<20;k++){
                acc[k] += __shfl_xor_sync(0xffffffffu, acc[k], 1);
                acc[k] += __shfl_xor_sync(0xffffffffu, acc[k], 2);
                acc[k] += __shfl_xor_sync(0xffffffffu, acc[k], 4);
            }
            if (chunk == 0){
                #pragma unroll
                for (int h=0;h<4;h++)
                    #pragma unroll
                    for (int c=0;c<5;c++)
                        shS[h*164 + t*5 + c] = acc[h*5+c];
            }
            if (tid < 160){
                int g = tid >> 3, ch = tid & 7;
                int h = g/5, c = g - h*5;
                float s = 0.f;
                for (int e = ch; e < M; e += 8)
                    s = fmaf(shLp[e][h], shY[e*8+c], s);
                s += __shfl_xor_sync(0xffffffffu, s, 1);
                s += __shfl_xor_sync(0xffffffffu, s, 2);
                s += __shfl_xor_sync(0xffffffffu, s, 4);
                if (ch == 0) shS0[h][c] = s;
            }
        }
        __syncthreads();
        if (wp == 0){
            int hh = lane >> 3;
            float P[5] = {0.f,0.f,0.f,0.f,0.f};
            const float* Sh = &shS[hh*164];
            #pragma unroll 8
            for (int t=0; t<32; t++){
                float rv = shR2v[t*32 + lane];
                #pragma unroll
                for (int c=0;c<5;c++) P[c] = fmaf(rv, Sh[t*5+c], P[c]);
            }
            float rb = shrb2v[lane];
            float o = 0.f;
            #pragma unroll
            for (int c=0;c<5;c++)
                o = fmaf(shMv[c*32+lane], fmaf(rb, shS0[hh][c], P[c]), o);
            oval = __fdividef(o, shsum[hh]);
        }
    }

    // ---- fused warp-0 epilogue: Wo0 + residual + FF + partial store ----
    if (wp == 0){
        float v[5];
        #pragma unroll
        for (int c=0;c<5;c++) v[c] = oval * shWo[lane*5+c];
        #pragma unroll
        for (int o=16;o;o>>=1){
            #pragma unroll
            for (int c=0;c<5;c++) v[c] += __shfl_xor_sync(0xffffffffu, v[c], o);
        }
        float x[5], n0[5], mu = 0.f;
        #pragma unroll
        for (int c=0;c<5;c++){
            x[c] = v[c] + feats[row*NC+c];
            n0[c] = fabsf(x[c]); mu += n0[c];
        }
        mu *= 0.2f;
        float var = 0.f;
        #pragma unroll
        for (int c=0;c<5;c++){ float d=n0[c]-mu; var=fmaf(d,d,var); }
        var *= 0.2f;
        float isd = __fdividef(1.f, sqrtf(var)+1e-8f);
        float yv[5];
        #pragma unroll
        for (int c=0;c<5;c++){
            float ln = (n0[c]-mu)*isd*gnF[c]+bnF[c];
            float g = gelu_t(ln);
            yv[c] = (x[c]>0.f)? g : ((x[c]<0.f)? -g : 0.f);
        }
        float f0[5] = {0.f,0.f,0.f,0.f,0.f};
        if (lane < NFF){
            float hsum = 0.f;
            #pragma unroll
            for (int c=0;c<5;c++) hsum = fmaf(yv[c], Wf1[c*NFF+lane], hsum);
            float hg = gelu_t(hsum);
            #pragma unroll
            for (int c=0;c<5;c++) f0[c] = hg*Wf2[lane*NC+c];
        }
        #pragma unroll
        for (int o=16;o;o>>=1){
            #pragma unroll
            for (int c=0;c<5;c++) f0[c] += __shfl_xor_sync(0xffffffffu, f0[c], o);
        }
        if (lane == 0){
            #pragma unroll
            for (int c=0;c<5;c++) g_part[c*(NB*NN)+row] = x[c]+f0[c];
            __threadfence();   // publish before ticket
        }
    }
    __syncthreads();

    // ---- hierarchical last-block-done gate ----
    if (tid == 0){
        unsigned fin = 0u;
        unsigned grp = (unsigned)(row >> 5);            // 16 groups of 32 blocks
        unsigned v = atomicAdd(&g_t1[grp], 1u);
        if (v == 31u){
            atomicExch(&g_t1[grp], 0u);
            unsigned w = atomicAdd(&g_t2, 1u);
            if (w == 15u){
                atomicExch(&g_t2, 0u);
                __threadfence();
                fin = 1u;
            }
        }
        sh_is_last = fin;
    }
    __syncthreads();
    if (!sh_is_last) return;

    // ---- final block: pooled reduction + head MLP ----
    #pragma unroll
    for (int bb=0; bb<NB; bb++){
        float v[5];
        #pragma unroll
        for (int c=0;c<5;c++) v[c] = g_part[c*(NB*NN) + bb*256 + tid];
        #pragma unroll
        for (int c=0;c<5;c++){
            float r = wredsum(v[c]);
            if (lane == 0) shred[wp][c] = r;
        }
        __syncthreads();
        if (tid < 5){
            float ss = 0.f;
            #pragma unroll
            for (int w=0; w<8; w++) ss += shred[w][tid];
            sp[bb][tid] = ss * (1.0f/(float)NN);
        }
        __syncthreads();
    }
    {
        int bb = tid >> 7, u = tid & 127;
        float sv = bh1[u];
        #pragma unroll
        for (int c=0;c<NC;c++) sv = fmaf(sp[bb][c], Wh1[c*128+u], sv);
        shh[bb][u] = fmaxf(sv, 0.f);
    }
    __syncthreads();
    for (int o = wp; o < NB*9; o += 8){
        int bb = o/9, oo = o%9;
        float sv = 0.f;
        for (int f = lane; f < 128; f += 32)
            sv = fmaf(shh[bb][f], Wh2[f*9+oo], sv);
        sv = wredsum(sv);
        if (lane == 0) out[o] = bh2[oo] + sv;
    }
}

// ---------------------------------------------------------------------------
extern "C" void kernel_launch(void* const* d_in, const int* in_sizes, int n_in,
                              void* d_out, int out_size){
    const float* feats = (const float*)d_in[0];
    const float* coors = (const float*)d_in[1];
    const void*  adj   = d_in[2];
    const float* Wq  = (const float*)d_in[3];
    const float* Mk  = (const float*)d_in[4];
    const float* Mv  = (const float*)d_in[5];
    const float* R1  = (const float*)d_in[6];
    const float* rb1 = (const float*)d_in[7];
    const float* R2  = (const float*)d_in[8];
    const float* rb2 = (const float*)d_in[9];
    const float* Wo0 = (const float*)d_in[10];
    const float* gnA = (const float*)d_in[12];
    const float* bnA = (const float*)d_in[13];
    const float* gnF = (const float*)d_in[14];
    const float* bnF = (const float*)d_in[15];
    const float* Wf1 = (const float*)d_in[16];
    const float* Wf2 = (const float*)d_in[17];
    const float* Wh1 = (const float*)d_in[20];
    const float* bh1 = (const float*)d_in[21];
    const float* Wh2 = (const float*)d_in[22];
    const float* bh2 = (const float*)d_in[23];
    float* out = (float*)d_out;

    attn_fused<<<NB*NN, 256>>>(feats, coors, adj, Wq, Mk, Mv,
                               R1, rb1, R2, rb2, Wo0,
                               gnA, bnA, gnF, bnF, Wf1, Wf2,
                               Wh1, bh1, Wh2, bh2, out);
}

// round 13
// speedup vs baseline: 1.1047x; 1.1047x over previous
#include <cuda_runtime.h>
#include <cuda_bf16.h>
#include <math.h>
#include <stdint.h>

#define NB 2
#define NN 256
#define NC 5
#define NFF 20

__device__ float    g_part[NC*NB*NN];   // planar [c][row]
__device__ unsigned g_t1[16];           // hierarchical ticket, level 1
__device__ unsigned g_t2 = 0;           // level 2

__device__ __forceinline__ float gelu_t(float x){
    float z = 1.5957691216057308f*fmaf(0.044715f*x, x*x, x);
    return __fdividef(x, 1.0f + __expf(-z));
}
__device__ __forceinline__ float wredsum(float v){
    #pragma unroll
    for (int o=16;o;o>>=1) v += __shfl_xor_sync(0xffffffffu, v, o);
    return v;
}
__device__ __forceinline__ float wredmax(float v){
    #pragma unroll
    for (int o=16;o;o>>=1) v = fmaxf(v, __shfl_xor_sync(0xffffffffu, v, o));
    return v;
}
__device__ __forceinline__ bool adjval(const void* a, int mode, long idx){
    if (mode == 1) return ((const int*)a)[idx] != 0;
    if (mode == 2) return ((const float*)a)[idx] != 0.f;
    return ((const unsigned char*)a)[idx] != 0;
}

// Slow (exact, general) logit evaluator — fallback only.
template<int K>
__device__ __forceinline__ void logits_eval(
    int M, int el, int h,
    const float* __restrict__ shDist, const float* __restrict__ shY,
    const float2* __restrict__ shR1b,
    const float* __restrict__ shA, const float* __restrict__ shA0p,
    float (*__restrict__ shLp)[4])
{
    float dist[K], yc[K];
    float4 y4[K];
    bool  val[K];
    #pragma unroll
    for (int k=0;k<K;k++){
        int e = el + 64*k;
        val[k] = (e < M);
        if (val[k]){
            dist[k] = shDist[e];
            y4[k] = *(const float4*)&shY[e*8];
            yc[k] = shY[e*8+4];
        } else {
            dist[k]=0.f; y4[k]=make_float4(0.f,0.f,0.f,0.f); yc[k]=0.f;
        }
    }
    float acc[K];
    #pragma unroll
    for (int k=0;k<K;k++) acc[k]=0.f;
    const float* Ah = shA + h*256;
    #pragma unroll 8
    for (int t=0;t<32;t++){
        float2 rb = shR1b[t];
        float4 a  = *(const float4*)&Ah[t*8];
        float  a4 = Ah[t*8+4];
        #pragma unroll
        for (int k=0;k<K;k++){
            float hv = fmaxf(fmaf(dist[k], rb.x, rb.y), 0.f);
            float tmp = fmaf(y4[k].x,a.x, fmaf(y4[k].y,a.y,
                        fmaf(y4[k].z,a.z, fmaf(y4[k].w,a.w, yc[k]*a4))));
            acc[k] = fmaf(hv, tmp, acc[k]);
        }
    }
    float4 a0 = *(const float4*)&shA0p[h*8];
    float a04 = shA0p[h*8+4];
    #pragma unroll
    for (int k=0;k<K;k++){
        if (val[k]){
            float l = acc[k] + fmaf(y4[k].x,a0.x, fmaf(y4[k].y,a0.y,
                      fmaf(y4[k].z,a0.z, fmaf(y4[k].w,a0.w, yc[k]*a04))));
            shLp[el+64*k][h] = l*0.35355339059327373f;
        }
    }
}

// ---------------------------------------------------------------------------
__global__ void __launch_bounds__(256,4)
attn_fused(const float* __restrict__ feats, const float* __restrict__ coors,
           const void*  __restrict__ adj,
           const float* __restrict__ Wq,  const float* __restrict__ Mk,
           const float* __restrict__ Mv,
           const float* __restrict__ R1,  const float* __restrict__ rb1,
           const float* __restrict__ R2,  const float* __restrict__ rb2,
           const float* __restrict__ Wo0,
           const float* __restrict__ gnA, const float* __restrict__ bnA,
           const float* __restrict__ gnF, const float* __restrict__ bnF,
           const float* __restrict__ Wf1, const float* __restrict__ Wf2,
           const float* __restrict__ Wh1, const float* __restrict__ bh1,
           const float* __restrict__ Wh2, const float* __restrict__ bh2,
           float* __restrict__ out){
    __shared__ float shR2k[1024], shR2v[1024];          // slow path only
    __shared__ float shMk[160], shMv[160], shqMk[160], shWo[160];
    __shared__ float2 shR1b[32];
    __shared__ float shrb2k[32], shrb2v[32], shq[32];
    __shared__ __align__(16) float shA[4*256];          // slow
    __shared__ __align__(16) float shA0p[32];           // slow
    __shared__ float shS[4*164];                        // slow
    __shared__ float shS0[4][5];                        // slow
    __shared__ __align__(16) float shY[256*8];
    __shared__ float shDist[256];
    __shared__ __align__(16) float shLp[256][4];
    __shared__ unsigned shlanes[8];
    __shared__ int shcnt[8];
    __shared__ unsigned char shdir[256], shlist[256];
    __shared__ float shred[8][5];
    __shared__ float shmax[4], shsum[4];
    __shared__ float shC[4][32];                        // Ck,Pk,Cv,Pv
    __shared__ float shLQ[20], shLPb[20];               // [h*5+c]
    __shared__ float shTD[44];                          // [0..3]=sum, [4..23]=T, [24..43]=D
    __shared__ unsigned sh_is_last;
    __shared__ float sp[NB][NC];
    __shared__ float shh[NB][128];

    int row = blockIdx.x;
    int b = row >> 8, i = row & 255;
    int tid = threadIdx.x;
    int lane = tid & 31, wp = tid >> 5;

    // ---- prologue: small weights, dtype detect (4KB scan), q0 ----
    if (tid < 160){ shMk[tid] = Mk[tid]; shMv[tid] = Mv[tid]; shWo[tid] = Wo0[tid]; }
    if (tid < 32){
        shR1b[tid] = make_float2(R1[tid], rb1[tid]);
        shrb2k[tid]=rb2[tid]; shrb2v[tid]=rb2[192+tid];
    }
    {
        unsigned m = 0;
        const uint32_t* aw = (const uint32_t*)adj;
        #pragma unroll
        for (int o=0;o<4;o++){
            uint32_t w = aw[o*256 + tid];
            m |= (w & 0x000000FFu ? 1u:0u) | (w & 0x0000FF00u ? 2u:0u)
               | (w & 0x00FF0000u ? 4u:0u) | (w & 0xFF000000u ? 8u:0u);
        }
        #pragma unroll
        for (int off=16; off; off>>=1) m |= __shfl_xor_sync(0xffffffffu, m, off);
        if (lane == 0) shlanes[wp] = m;
    }
    if (tid >= 32 && tid < 64){            // q0
        int hd = tid - 32;
        float xv[NC], n0[NC], mu = 0.f;
        #pragma unroll
        for (int c=0;c<NC;c++){ xv[c]=feats[row*NC+c]; n0[c]=fabsf(xv[c]); mu += n0[c]; }
        mu *= 0.2f;
        float var = 0.f;
        #pragma unroll
        for (int c=0;c<NC;c++){ float d=n0[c]-mu; var = fmaf(d,d,var); }
        var *= 0.2f;
        float isd = __fdividef(1.f, sqrtf(var) + 1e-8f);
        float q = 0.f;
        #pragma unroll
        for (int c=0;c<NC;c++){
            float ln = (n0[c]-mu)*isd * gnA[c] + bnA[c];
            float g = gelu_t(ln);
            float y = (xv[c] > 0.f) ? g : ((xv[c] < 0.f) ? -g : 0.f);
            q = fmaf(y, Wq[c*32+hd], q);
        }
        shq[hd] = q;
    }
    __syncthreads();

    unsigned lm = 0;
    #pragma unroll
    for (int w=0; w<8; w++) lm |= shlanes[w];
    int mode = ((lm & 0xEu) == 0) ? 1 : (((lm & 0x3u) == 0) ? 2 : 0);

    if (tid < 160) shqMk[tid] = shq[tid & 31] * shMk[tid];

    // ---- adjacency: direct row -> dir list ----
    bool okd = adjval(adj, mode, (long)row*NN + tid);
    unsigned bald = __ballot_sync(0xffffffffu, okd);
    if (lane == 0) shcnt[wp] = __popc(bald);
    __syncthreads();
    int based = 0, Mdir = 0;
    #pragma unroll
    for (int w=0; w<8; w++){ if (w < wp) based += shcnt[w]; Mdir += shcnt[w]; }
    if (okd) shdir[based + __popc(bald & ((1u<<lane)-1u))] = (unsigned char)tid;
    __syncthreads();

    // ---- 2-hop: per-thread OR over direct neighbors' rows (coalesced) ----
    bool col2 = false;
    {
        long bb = (long)(b*NN)*NN;
        int d = 0;
        for (; d+4 <= Mdir; d += 4){
            long j0 = bb + (long)shdir[d+0]*NN + tid;
            long j1 = bb + (long)shdir[d+1]*NN + tid;
            long j2 = bb + (long)shdir[d+2]*NN + tid;
            long j3 = bb + (long)shdir[d+3]*NN + tid;
            col2 |= adjval(adj,mode,j0) | adjval(adj,mode,j1)
                  | adjval(adj,mode,j2) | adjval(adj,mode,j3);
        }
        for (; d < Mdir; d++)
            col2 |= adjval(adj, mode, bb + (long)shdir[d]*NN + tid);
    }
    bool ok = okd | col2 | (tid == i);

    // compaction of active j's (ascending)
    unsigned bal = __ballot_sync(0xffffffffu, ok);
    if (lane == 0) shcnt[wp] = __popc(bal);
    __syncthreads();
    int base = 0, M = 0;
    #pragma unroll
    for (int w=0; w<8; w++){ if (w < wp) base += shcnt[w]; M += shcnt[w]; }
    if (ok) shlist[base + __popc(bal & ((1u<<lane)-1u))] = (unsigned char)tid;
    __syncthreads();

    // ---- E1: per-edge dist + normalized y[5] (thread = edge) ----
    bool act_e = (tid < M);
    float y5[5] = {0.f,0.f,0.f,0.f,0.f};
    float de = 0.f;
    {
        float cx = coors[row*3+0], cy = coors[row*3+1], cz = coors[row*3+2];
        if (act_e){
            int jr = (b << 8) + (int)shlist[tid];
            float dx = cx - coors[jr*3+0];
            float dy = cy - coors[jr*3+1];
            float dz = cz - coors[jr*3+2];
            de = sqrtf(fmaf(dx,dx,fmaf(dy,dy,fmaf(dz,dz,1e-12f))));
            shDist[tid] = de;
            float xv[NC], n0[NC], mu = 0.f;
            #pragma unroll
            for (int c=0;c<NC;c++){ xv[c]=feats[jr*NC+c]; n0[c]=fabsf(xv[c]); mu += n0[c]; }
            mu *= 0.2f;
            float var = 0.f;
            #pragma unroll
            for (int c=0;c<NC;c++){ float d=n0[c]-mu; var = fmaf(d,d,var); }
            var *= 0.2f;
            float isd = __fdividef(1.f, sqrtf(var) + 1e-8f);
            #pragma unroll
            for (int c=0;c<NC;c++){
                float ln = (n0[c]-mu)*isd * gnA[c] + bnA[c];
                float g = gelu_t(ln);
                y5[c] = (xv[c] > 0.f) ? g : ((xv[c] < 0.f) ? -g : 0.f);
                shY[tid*8+c] = y5[c];
            }
        }
        float dmn = act_e ? de : 1e30f;
        float dmx = act_e ? de : -1e30f;
        #pragma unroll
        for (int o=16;o;o>>=1){
            dmn = fminf(dmn, __shfl_xor_sync(0xffffffffu, dmn, o));
            dmx = fmaxf(dmx, __shfl_xor_sync(0xffffffffu, dmx, o));
        }
        if (lane == 0){ shred[wp][0] = dmn; shred[wp][1] = dmx; }
    }
    __syncthreads();

    // ---- linearity check: redundantly in EVERY warp ----
    unsigned actm;
    bool slow;
    {
        float dmin = 1e30f, dmax = -1e30f;
        #pragma unroll
        for (int w=0; w<8; w++){
            dmin = fminf(dmin, shred[w][0]);
            dmax = fmaxf(dmax, shred[w][1]);
        }
        float2 rb = shR1b[lane];
        float x1 = fmaf(dmin, rb.x, rb.y);
        float x2 = fmaf(dmax, rb.x, rb.y);
        float xlo = fminf(x1,x2), xhi = fmaxf(x1,x2);
        actm = __ballot_sync(0xffffffffu, xhi > 0.f);
        unsigned badm = __ballot_sync(0xffffffffu, (xlo < 0.f) && (xhi > 0.f));
        slow = (badm != 0u);
    }

    float oval = 0.f;   // warp-0 per-lane o0[lane], set by either path

    if (!slow){
        // ================= FAST (linear) PATH =================
        if (tid < 128){
            int kind = tid >> 5, hd = tid & 31;
            int off = (kind < 2) ? hd : (192 + hd);
            float acc = 0.f;
            #pragma unroll 4
            for (int t=0; t<32; t++){
                if ((actm >> t) & 1u){
                    float2 rb = shR1b[t];
                    float w = (kind & 1) ? rb.y : rb.x;
                    acc = fmaf(w, R2[t*384 + off], acc);
                }
            }
            shC[kind][hd] = acc;
        }
        __syncthreads();
        if (tid < 20){
            int h = tid / 5, c = tid - h*5;
            float lq = 0.f, lp = 0.f;
            #pragma unroll
            for (int dd=0; dd<8; dd++){
                float qm = shqMk[c*32 + h*8 + dd];
                lq = fmaf(qm, shC[0][h*8+dd], lq);
                lp = fmaf(qm, shrb2k[h*8+dd] + shC[1][h*8+dd], lp);
            }
            shLQ[tid] = lq; shLPb[tid] = lp;
        }
        __syncthreads();

        // logits in registers
        float lg[4];
        #pragma unroll
        for (int h=0; h<4; h++){
            float l = 0.f;
            #pragma unroll
            for (int c=0; c<5; c++)
                l = fmaf(y5[c], fmaf(de, shLQ[h*5+c], shLPb[h*5+c]), l);
            lg[h] = act_e ? l*0.35355339059327373f : -1e30f;
        }
        #pragma unroll
        for (int h=0; h<4; h++){
            float mm = wredmax(lg[h]);
            if (lane == 0) shred[wp][h] = mm;
        }
        __syncthreads();
        if (tid < 4){
            float mm = -1e30f;
            #pragma unroll
            for (int w=0; w<8; w++) mm = fmaxf(mm, shred[w][tid]);
            shmax[tid] = mm;
        }
        __syncthreads();
        if (act_e){
            float4 L;
            L.x = __expf(lg[0]-shmax[0]);
            L.y = __expf(lg[1]-shmax[1]);
            L.z = __expf(lg[2]-shmax[2]);
            L.w = __expf(lg[3]-shmax[3]);
            *(float4*)&shLp[tid][0] = L;
        }
        __syncthreads();

        // moments via smem-transpose consumers
        if (tid < 160){
            int g = tid >> 3, ch = tid & 7;
            int h = g/5, c = g - h*5;
            float T = 0.f, D = 0.f;
            for (int e = ch; e < M; e += 8){
                float ly = shLp[e][h]*shY[e*8+c];
                T += ly;
                D = fmaf(ly, shDist[e], D);
            }
            #pragma unroll
            for (int o=1; o<8; o<<=1){
                T += __shfl_xor_sync(0xffffffffu, T, o);
                D += __shfl_xor_sync(0xffffffffu, D, o);
            }
            if (ch == 0){ shTD[4+g] = T; shTD[24+g] = D; }
        } else if (tid < 192){
            int k = tid - 160;
            int h = k >> 3, ch = k & 7;
            float s = 0.f;
            for (int e = ch; e < M; e += 8) s += shLp[e][h];
            #pragma unroll
            for (int o=1; o<8; o<<=1) s += __shfl_xor_sync(0xffffffffu, s, o);
            if (ch == 0) shTD[h] = s;
        }
        __syncthreads();

        if (wp == 0){
            int hh = lane >> 3;
            float cst = shrb2v[lane] + shC[3][lane];   // rb2v + Pv
            float cv  = shC[2][lane];                  // Cv
            float o = 0.f;
            #pragma unroll
            for (int c=0;c<5;c++)
                o = fmaf(shMv[c*32+lane],
                         fmaf(cst, shTD[4+hh*5+c], cv*shTD[24+hh*5+c]), o);
            oval = __fdividef(o, shTD[hh]);
        }
    } else {
        // ================= SLOW (exact) PATH =================
        for (int s=tid; s<1024; s+=256){
            int t = s >> 5, hd = s & 31;
            shR2k[s] = R2[t*384 + hd];
            shR2v[s] = R2[t*384 + 192 + hd];
        }
        __syncthreads();
        for (int idx = tid; idx < 660; idx += 256){
            if (idx < 640){
                int h = idx / 160, r = idx - h*160, t = r/5, c = r - t*5;
                float s = 0.f;
                #pragma unroll
                for (int d=0; d<8; d++)
                    s = fmaf(shqMk[c*32 + h*8 + d], shR2k[t*32 + h*8 + d], s);
                shA[h*256 + t*8 + c] = s;
            } else {
                int k = idx - 640, h = k/5, c = k - h*5;
                float s = 0.f;
                #pragma unroll
                for (int d=0; d<8; d++)
                    s = fmaf(shqMk[c*32 + h*8 + d], shrb2k[h*8 + d], s);
                shA0p[h*8 + c] = s;
            }
        }
        if (act_e){ shY[tid*8+5]=0.f; shY[tid*8+6]=0.f; shY[tid*8+7]=0.f; }
        __syncthreads();
        {
            int h = tid & 3;
            int el = tid >> 2;
            int kmax = (M + 63) >> 6;
            switch (kmax){
                case 1: logits_eval<1>(M, el, h, shDist, shY, shR1b, shA, shA0p, shLp); break;
                case 2: logits_eval<2>(M, el, h, shDist, shY, shR1b, shA, shA0p, shLp); break;
                case 3: logits_eval<3>(M, el, h, shDist, shY, shR1b, shA, shA0p, shLp); break;
                default: logits_eval<4>(M, el, h, shDist, shY, shR1b, shA, shA0p, shLp); break;
            }
        }
        __syncthreads();
        {
            float4 lv4 = (tid < M) ? *(const float4*)&shLp[tid][0]
                                   : make_float4(-1e30f,-1e30f,-1e30f,-1e30f);
            float lv[4] = {lv4.x, lv4.y, lv4.z, lv4.w};
            #pragma unroll
            for (int hh=0; hh<4; hh++){
                float mm = wredmax(lv[hh]);
                if (lane == 0) shred[wp][hh] = mm;
            }
            __syncthreads();
            if (tid < 4){
                float mm = -1e30f;
                #pragma unroll
                for (int w=0; w<8; w++) mm = fmaxf(mm, shred[w][tid]);
                shmax[tid] = mm;
            }
            __syncthreads();
            float ex[4];
            #pragma unroll
            for (int hh=0; hh<4; hh++) ex[hh] = (tid < M) ? __expf(lv[hh]-shmax[hh]) : 0.f;
            if (tid < M)
                *(float4*)&shLp[tid][0] = make_float4(ex[0],ex[1],ex[2],ex[3]);
            #pragma unroll
            for (int hh=0; hh<4; hh++){
                float ss = wredsum(ex[hh]);
                if (lane == 0) shred[wp][hh] = ss;
            }
            __syncthreads();
            if (tid < 4){
                float ss = 0.f;
                #pragma unroll
                for (int w=0; w<8; w++) ss += shred[w][tid];
                shsum[tid] = ss;
            }
            __syncthreads();
        }
        {
            int chunk = tid & 7, t = tid >> 3;
            float2 rb = shR1b[t];
            float acc[20];
            #pragma unroll
            for (int k=0;k<20;k++) acc[k]=0.f;
            for (int e = chunk; e < M; e += 8){
                float hv = fmaxf(fmaf(shDist[e], rb.x, rb.y), 0.f);
                float4 L4 = *(const float4*)&shLp[e][0];
                float4 y4 = *(const float4*)&shY[e*8];
                float  yc = shY[e*8+4];
                float p0 = L4.x*hv, p1 = L4.y*hv, p2 = L4.z*hv, p3 = L4.w*hv;
                acc[0] = fmaf(p0,y4.x,acc[0]);  acc[1] = fmaf(p0,y4.y,acc[1]);
                acc[2] = fmaf(p0,y4.z,acc[2]);  acc[3] = fmaf(p0,y4.w,acc[3]);
                acc[4] = fmaf(p0,yc,  acc[4]);
                acc[5] = fmaf(p1,y4.x,acc[5]);  acc[6] = fmaf(p1,y4.y,acc[6]);
                acc[7] = fmaf(p1,y4.z,acc[7]);  acc[8] = fmaf(p1,y4.w,acc[8]);
                acc[9] = fmaf(p1,yc,  acc[9]);
                acc[10]= fmaf(p2,y4.x,acc[10]); acc[11]= fmaf(p2,y4.y,acc[11]);
                acc[12]= fmaf(p2,y4.z,acc[12]); acc[13]= fmaf(p2,y4.w,acc[13]);
                acc[14]= fmaf(p2,yc,  acc[14]);
                acc[15]= fmaf(p3,y4.x,acc[15]); acc[16]= fmaf(p3,y4.y,acc[16]);
                acc[17]= fmaf(p3,y4.z,acc[17]); acc[18]= fmaf(p3,y4.w,acc[18]);
                acc[19]= fmaf(p3,yc,  acc[19]);
            }
            #pragma unroll
            for (int k=0;k<20;k++){
                acc[k] += __shfl_xor_sync(0xffffffffu, acc[k], 1);
                acc[k] += __shfl_xor_sync(0xffffffffu, acc[k], 2);
                acc[k] += __shfl_xor_sync(0xffffffffu, acc[k], 4);
            }
            if (chunk == 0){
                #pragma unroll
                for (int h=0;h<4;h++)
                    #pragma unroll
                    for (int c=0;c<5;c++)
                        shS[h*164 + t*5 + c] = acc[h*5+c];
            }
            if (tid < 160){
                int g = tid >> 3, ch = tid & 7;
                int h = g/5, c = g - h*5;
                float s = 0.f;
                for (int e = ch; e < M; e += 8)
                    s = fmaf(shLp[e][h], shY[e*8+c], s);
                s += __shfl_xor_sync(0xffffffffu, s, 1);
                s += __shfl_xor_sync(0xffffffffu, s, 2);
                s += __shfl_xor_sync(0xffffffffu, s, 4);
                if (ch == 0) shS0[h][c] = s;
            }
        }
        __syncthreads();
        if (wp == 0){
            int hh = lane >> 3;
            float P[5] = {0.f,0.f,0.f,0.f,0.f};
            const float* Sh = &shS[hh*164];
            #pragma unroll 8
            for (int t=0; t<32; t++){
                float rv = shR2v[t*32 + lane];
                #pragma unroll
                for (int c=0;c<5;c++) P[c] = fmaf(rv, Sh[t*5+c], P[c]);
            }
            float rb = shrb2v[lane];
            float o = 0.f;
            #pragma unroll
            for (int c=0;c<5;c++)
                o = fmaf(shMv[c*32+lane], fmaf(rb, shS0[hh][c], P[c]), o);
            oval = __fdividef(o, shsum[hh]);
        }
    }

    // ---- fused warp-0 epilogue: Wo0 + residual + FF + partial store ----
    if (wp == 0){
        float v[5];
        #pragma unroll
        for (int c=0;c<5;c++) v[c] = oval * shWo[lane*5+c];
        #pragma unroll
        for (int o=16;o;o>>=1){
            #pragma unroll
            for (int c=0;c<5;c++) v[c] += __shfl_xor_sync(0xffffffffu, v[c], o);
        }
        float x[5], n0[5], mu = 0.f;
        #pragma unroll
        for (int c=0;c<5;c++){
            x[c] = v[c] + feats[row*NC+c];
            n0[c] = fabsf(x[c]); mu += n0[c];
        }
        mu *= 0.2f;
        float var = 0.f;
        #pragma unroll
        for (int c=0;c<5;c++){ float d=n0[c]-mu; var=fmaf(d,d,var); }
        var *= 0.2f;
        float isd = __fdividef(1.f, sqrtf(var)+1e-8f);
        float yv[5];
        #pragma unroll
        for (int c=0;c<5;c++){
            float ln = (n0[c]-mu)*isd*gnF[c]+bnF[c];
            float g = gelu_t(ln);
            yv[c] = (x[c]>0.f)? g : ((x[c]<0.f)? -g : 0.f);
        }
        float f0[5] = {0.f,0.f,0.f,0.f,0.f};
        if (lane < NFF){
            float hsum = 0.f;
            #pragma unroll
            for (int c=0;c<5;c++) hsum = fmaf(yv[c], Wf1[c*NFF+lane], hsum);
            float hg = gelu_t(hsum);
            #pragma unroll
            for (int c=0;c<5;c++) f0[c] = hg*Wf2[lane*NC+c];
        }
        #pragma unroll
        for (int o=16;o;o>>=1){
            #pragma unroll
            for (int c=0;c<5;c++) f0[c] += __shfl_xor_sync(0xffffffffu, f0[c], o);
        }
        if (lane == 0){
            #pragma unroll
            for (int c=0;c<5;c++) g_part[c*(NB*NN)+row] = x[c]+f0[c];
            __threadfence();   // publish before ticket
        }
    }
    __syncthreads();

    // ---- hierarchical last-block-done gate ----
    if (tid == 0){
        unsigned fin = 0u;
        unsigned grp = (unsigned)(row >> 5);            // 16 groups of 32 blocks
        unsigned v = atomicAdd(&g_t1[grp], 1u);
        if (v == 31u){
            atomicExch(&g_t1[grp], 0u);
            unsigned w = atomicAdd(&g_t2, 1u);
            if (w == 15u){
                atomicExch(&g_t2, 0u);
                __threadfence();
                fin = 1u;
            }
        }
        sh_is_last = fin;
    }
    __syncthreads();
    if (!sh_is_last) return;

    // ---- final block: pooled reduction + head MLP ----
    #pragma unroll
    for (int bb=0; bb<NB; bb++){
        float v[5];
        #pragma unroll
        for (int c=0;c<5;c++) v[c] = g_part[c*(NB*NN) + bb*256 + tid];
        #pragma unroll
        for (int c=0;c<5;c++){
            float r = wredsum(v[c]);
            if (lane == 0) shred[wp][c] = r;
        }
        __syncthreads();
        if (tid < 5){
            float ss = 0.f;
            #pragma unroll
            for (int w=0; w<8; w++) ss += shred[w][tid];
            sp[bb][tid] = ss * (1.0f/(float)NN);
        }
        __syncthreads();
    }
    {
        int bb = tid >> 7, u = tid & 127;
        float sv = bh1[u];
        #pragma unroll
        for (int c=0;c<NC;c++) sv = fmaf(sp[bb][c], Wh1[c*128+u], sv);
        shh[bb][u] = fmaxf(sv, 0.f);
    }
    __syncthreads();
    for (int o = wp; o < NB*9; o += 8){
        int bb = o/9, oo = o%9;
        float sv = 0.f;
        for (int f = lane; f < 128; f += 32)
            sv = fmaf(shh[bb][f], Wh2[f*9+oo], sv);
        sv = wredsum(sv);
        if (lane == 0) out[o] = bh2[oo] + sv;
    }
}

// ---------------------------------------------------------------------------
extern "C" void kernel_launch(void* const* d_in, const int* in_sizes, int n_in,
                              void* d_out, int out_size){
    const float* feats = (const float*)d_in[0];
    const float* coors = (const float*)d_in[1];
    const void*  adj   = d_in[2];
    const float* Wq  = (const float*)d_in[3];
    const float* Mk  = (const float*)d_in[4];
    const float* Mv  = (const float*)d_in[5];
    const float* R1  = (const float*)d_in[6];
    const float* rb1 = (const float*)d_in[7];
    const float* R2  = (const float*)d_in[8];
    const float* rb2 = (const float*)d_in[9];
    const float* Wo0 = (const float*)d_in[10];
    const float* gnA = (const float*)d_in[12];
    const float* bnA = (const float*)d_in[13];
    const float* gnF = (const float*)d_in[14];
    const float* bnF = (const float*)d_in[15];
    const float* Wf1 = (const float*)d_in[16];
    const float* Wf2 = (const float*)d_in[17];
    const float* Wh1 = (const float*)d_in[20];
    const float* bh1 = (const float*)d_in[21];
    const float* Wh2 = (const float*)d_in[22];
    const float* bh2 = (const float*)d_in[23];
    float* out = (float*)d_out;

    attn_fused<<<NB*NN, 256>>>(feats, coors, adj, Wq, Mk, Mv,
                               R1, rb1, R2, rb2, Wo0,
                               gnA, bnA, gnF, bnF, Wf1, Wf2,
                               Wh1, bh1, Wh2, bh2, out);
}